// round 14
// baseline (speedup 1.0000x reference)
#include <cuda_runtime.h>
#include <cuda_fp16.h>
#include <math.h>
#include <stdint.h>

#define BB 8
#define TT 2048
#define SS 2048
#define DD 256
#define NCHUNK 16
#define TCH 128   /* TT / NCHUNK */
#define NSBLK 16  /* SS / 128 */

#define CH_K 64                          /* fp16 elems per k-chunk */
#define PITCH 72                         /* fp16 pitch: bank = 4g+tg, conflict-free */
#define TILE_SMEM (128 * PITCH * 2)      /* 18432 B */
#define BUF_SZ (4 * TILE_SMEM)           /* 73728 B : 4-tile stage (hi/lo A,B) */
#define GSM_TOTAL (2 * BUF_SZ)           /* 147456 B, 2-stage */
#define BUF2 (2 * TILE_SMEM)             /* 36864 B : 2-tile stage (hi-only) */
#define GSM2 (2 * BUF2)                  /* 73728 B -> 2+ CTAs/SM */

// ---------------- scratch (device globals; no runtime allocation) ----------------
// ZERO-INVARIANT: regions with s >= len[b] of g_align / g_avh are NEVER written
// with nonzero values by any kernel; they stay 0 across all graph replays.
__device__ float        g_align [(size_t)BB * TT * SS]; // e_blk (fp32)
__device__ __half       g_avh   [(size_t)BB * TT * SS]; // fp16 of normalized av
__device__ float        g_bmax  [(size_t)BB * TT * NSBLK];
__device__ unsigned int g_rowmax[BB * TT];
__device__ float        g_carry [BB * NCHUNK * SS];     // raw per-chunk column sums
__device__ __half       g_chi   [(size_t)BB * TT * DD]; // context hi/lo fp16
__device__ __half       g_clo   [(size_t)BB * TT * DD];
__device__ __half       g_srchi [(size_t)BB * TT * DD];
__device__ __half       g_srclo [(size_t)BB * TT * DD];
__device__ __half       g_mbhi  [(size_t)BB * SS * DD];
__device__ __half       g_mblo  [(size_t)BB * SS * DD];
__device__ __half       g_mbthi [(size_t)BB * DD * SS]; // transposed [B,D,S], hi only
__device__ __half       g_wthi  [(size_t)DD * 2 * DD];  // W^T [D, 2D] hi/lo
__device__ __half       g_wtlo  [(size_t)DD * 2 * DD];

// ---------------- generic helpers ----------------
__device__ __forceinline__ unsigned fenc(float f) {
    unsigned u = __float_as_uint(f);
    return (u & 0x80000000u) ? ~u : (u | 0x80000000u);
}
__device__ __forceinline__ float fdec(unsigned e) {
    return (e & 0x80000000u) ? __uint_as_float(e ^ 0x80000000u) : __uint_as_float(~e);
}
__device__ __forceinline__ int decode_len(const int* __restrict__ lens32, int b) {
    bool is64 = (lens32[1] == 0) && (lens32[3] == 0) && (lens32[5] == 0) && (lens32[7] == 0);
    if (is64) return (int)((const long long*)lens32)[b];
    return lens32[b];
}
__device__ __forceinline__ void hsplit(float x, __half& h, __half& l) {
    h = __float2half_rn(x);
    l = __float2half_rn(x - __half2float(h));
}
__device__ __forceinline__ uint32_t smem_u32(const void* p) {
    uint32_t a;
    asm("{ .reg .u64 t; cvta.to.shared.u64 t, %1; cvt.u32.u64 %0, t; }" : "=r"(a) : "l"(p));
    return a;
}

// ---------------- cp.async + fp16 mma.sync infra ----------------
__device__ __forceinline__ void cp16(uint32_t dst, const void* src) {
    asm volatile("cp.async.cg.shared.global [%0], [%1], 16;" :: "r"(dst), "l"(src));
}
__device__ __forceinline__ void cp_commit() { asm volatile("cp.async.commit_group;" ::: "memory"); }
__device__ __forceinline__ void cp_wait0()  { asm volatile("cp.async.wait_group 0;" ::: "memory"); }

// one 128-row x 64-fp16 tile (128B/row) into pitched smem
__device__ __forceinline__ void ld_chunk16(uint32_t smbase, const __half* src, size_t stride, int tid) {
    int r0 = tid >> 3, c = tid & 7;
#pragma unroll
    for (int p = 0; p < 4; ++p) {
        int row = r0 + p * 32;
        cp16(smbase + row * (PITCH * 2) + c * 16, src + (size_t)row * stride + c * 8);
    }
}
__device__ __forceinline__ void ld_stage16(uint32_t stbase,
        const __half* Ah, const __half* Al, size_t sA,
        const __half* Bh, const __half* Bl, size_t sB, size_t ko, int tid) {
    ld_chunk16(stbase + 0 * TILE_SMEM, Ah + ko, sA, tid);
    ld_chunk16(stbase + 1 * TILE_SMEM, Al + ko, sA, tid);
    ld_chunk16(stbase + 2 * TILE_SMEM, Bh + ko, sB, tid);
    ld_chunk16(stbase + 3 * TILE_SMEM, Bl + ko, sB, tid);
    cp_commit();
}

__device__ __forceinline__ void mma_f16(float* d, uint32_t a0, uint32_t a1, uint32_t a2, uint32_t a3,
                                        uint32_t b0, uint32_t b1) {
    asm volatile("mma.sync.aligned.m16n8k16.row.col.f32.f16.f16.f32 "
                 "{%0,%1,%2,%3}, {%4,%5,%6,%7}, {%8,%9}, {%0,%1,%2,%3};"
                 : "+f"(d[0]), "+f"(d[1]), "+f"(d[2]), "+f"(d[3])
                 : "r"(a0), "r"(a1), "r"(a2), "r"(a3), "r"(b0), "r"(b1));
}
__device__ __forceinline__ uint32_t hld(const __half* p) { return *(const uint32_t*)p; }

// 3-term chunk (hi/lo A + hi/lo B in one 4-tile stage)
__device__ __forceinline__ void mma_chunk16(const char* stage, int wm, int wn, int g, int tg,
                                            float acc[4][4][4]) {
    const __half* Ash = (const __half*)stage;
    const __half* Asl = Ash + 128 * PITCH;
    const __half* Bsh = Asl + 128 * PITCH;
    const __half* Bsl = Bsh + 128 * PITCH;
#pragma unroll
    for (int ks = 0; ks < 4; ++ks) {
        int k0 = ks * 16;
        uint32_t bh[4][2], bl[4][2];
#pragma unroll
        for (int nt = 0; nt < 4; ++nt) {
            int o = (wn * 32 + nt * 8 + g) * PITCH + k0 + 2 * tg;
            bh[nt][0] = hld(Bsh + o);
            bh[nt][1] = hld(Bsh + o + 8);
            bl[nt][0] = hld(Bsl + o);
            bl[nt][1] = hld(Bsl + o + 8);
        }
#pragma unroll
        for (int mt = 0; mt < 4; ++mt) {
            int o = (wm * 64 + mt * 16 + g) * PITCH + k0 + 2 * tg;
            uint32_t ah0 = hld(Ash + o);
            uint32_t ah1 = hld(Ash + o + 8 * PITCH);
            uint32_t ah2 = hld(Ash + o + 8);
            uint32_t ah3 = hld(Ash + o + 8 * PITCH + 8);
            uint32_t al0 = hld(Asl + o);
            uint32_t al1 = hld(Asl + o + 8 * PITCH);
            uint32_t al2 = hld(Asl + o + 8);
            uint32_t al3 = hld(Asl + o + 8 * PITCH + 8);
#pragma unroll
            for (int nt = 0; nt < 4; ++nt) {
                mma_f16(acc[mt][nt], ah0, ah1, ah2, ah3, bl[nt][0], bl[nt][1]);
                mma_f16(acc[mt][nt], al0, al1, al2, al3, bh[nt][0], bh[nt][1]);
                mma_f16(acc[mt][nt], ah0, ah1, ah2, ah3, bh[nt][0], bh[nt][1]);
            }
        }
    }
}

// 1-term chunk (hi A + hi B in one 2-tile stage)
__device__ __forceinline__ void mma_chunk16_1(const char* stage, int wm, int wn, int g, int tg,
                                              float acc[4][4][4]) {
    const __half* Ash = (const __half*)stage;
    const __half* Bsh = Ash + 128 * PITCH;
#pragma unroll
    for (int ks = 0; ks < 4; ++ks) {
        int k0 = ks * 16;
        uint32_t b[4][2];
#pragma unroll
        for (int nt = 0; nt < 4; ++nt) {
            int o = (wn * 32 + nt * 8 + g) * PITCH + k0 + 2 * tg;
            b[nt][0] = hld(Bsh + o);
            b[nt][1] = hld(Bsh + o + 8);
        }
#pragma unroll
        for (int mt = 0; mt < 4; ++mt) {
            int o = (wm * 64 + mt * 16 + g) * PITCH + k0 + 2 * tg;
            uint32_t a0 = hld(Ash + o);
            uint32_t a1 = hld(Ash + o + 8 * PITCH);
            uint32_t a2 = hld(Ash + o + 8);
            uint32_t a3 = hld(Ash + o + 8 * PITCH + 8);
#pragma unroll
            for (int nt = 0; nt < 4; ++nt)
                mma_f16(acc[mt][nt], a0, a1, a2, a3, b[nt][0], b[nt][1]);
        }
    }
}

// 2-stage pipelined 3-term mainloop
__device__ __forceinline__ void tc_loop16(char* smem,
        const __half* __restrict__ Ah, const __half* __restrict__ Al, size_t sA,
        const __half* __restrict__ Bh, const __half* __restrict__ Bl, size_t sB,
        int nck, float acc[4][4][4]) {
    const int tid = threadIdx.x;
    const int lane = tid & 31, wid = tid >> 5;
    const int wm = wid >> 2, wn = wid & 3;
    const int g = lane >> 2, tg = lane & 3;
    uint32_t sb = smem_u32(smem);

#pragma unroll
    for (int i = 0; i < 4; ++i)
#pragma unroll
        for (int j = 0; j < 4; ++j)
#pragma unroll
            for (int q = 0; q < 4; ++q) acc[i][j][q] = 0.f;

    ld_stage16(sb, Ah, Al, sA, Bh, Bl, sB, 0, tid);

    int buf = 0;
    for (int ck = 0; ck < nck; ++ck) {
        cp_wait0();
        __syncthreads();
        if (ck + 1 < nck)
            ld_stage16(sb + (buf ^ 1) * BUF_SZ, Ah, Al, sA, Bh, Bl, sB, (size_t)(ck + 1) * CH_K, tid);
        mma_chunk16(smem + buf * BUF_SZ, wm, wn, g, tg, acc);
        buf ^= 1;
    }
}

// ---------------- split fp32 -> (fp16 hi, fp16 lo) elementwise (src) ----------------
__global__ void k_split_h(const float4* __restrict__ x, __half* __restrict__ hi,
                          __half* __restrict__ lo, int n4) {
    int i = blockIdx.x * 256 + threadIdx.x;
    if (i >= n4) return;
    float4 v = x[i];
    __half h0, h1, h2, h3, l0, l1, l2, l3;
    hsplit(v.x, h0, l0); hsplit(v.y, h1, l1);
    hsplit(v.z, h2, l2); hsplit(v.w, h3, l3);
    ((__half2*)hi)[2 * i]     = __halves2half2(h0, h1);
    ((__half2*)hi)[2 * i + 1] = __halves2half2(h2, h3);
    ((__half2*)lo)[2 * i]     = __halves2half2(l0, l1);
    ((__half2*)lo)[2 * i + 1] = __halves2half2(l2, l3);
}

// ---------------- single-read mb pipeline: hi/lo row-major + transposed hi ----------------
__global__ void k_mbsplit(const float* __restrict__ mb) {
    __shared__ float tile[32][33];
    int tx = threadIdx.x & 31, ty = threadIdx.x >> 5;
    int s0 = blockIdx.x * 32, d0 = blockIdx.y * 32, b = blockIdx.z;
#pragma unroll
    for (int j = 0; j < 4; ++j) {
        float x = mb[((size_t)b * SS + s0 + ty + j * 8) * DD + d0 + tx];
        tile[ty + j * 8][tx] = x;
        __half h, l;
        hsplit(x, h, l);
        size_t o = ((size_t)b * SS + s0 + ty + j * 8) * DD + d0 + tx;
        g_mbhi[o] = h;
        g_mblo[o] = l;
    }
    __syncthreads();
#pragma unroll
    for (int j = 0; j < 4; ++j) {
        float x = tile[tx][ty + j * 8];
        size_t o = ((size_t)b * DD + d0 + ty + j * 8) * SS + s0 + tx;
        g_mbthi[o] = __float2half_rn(x);
    }
}

// ---------------- W split (+ rowmax init piggyback) ----------------
__global__ void k_wsplit(const float* __restrict__ W) {
    int flat = (blockIdx.y * gridDim.x + blockIdx.x) * 256 + threadIdx.x;
    if (flat < BB * TT) g_rowmax[flat] = 0x007FFFFFu;  // fenc(-inf)

    __shared__ float tile[32][33];
    int tx = threadIdx.x & 31, ty = threadIdx.x >> 5;
    int k0 = blockIdx.x * 32, n0 = blockIdx.y * 32;
#pragma unroll
    for (int j = 0; j < 4; ++j)
        tile[ty + j * 8][tx] = W[(size_t)(k0 + ty + j * 8) * DD + n0 + tx];
    __syncthreads();
#pragma unroll
    for (int j = 0; j < 4; ++j) {
        float x = tile[tx][ty + j * 8];
        __half h, l;
        hsplit(x, h, l);
        size_t o = (size_t)(n0 + ty + j * 8) * (2 * DD) + k0 + tx;
        g_wthi[o] = h;
        g_wtlo[o] = l;
    }
}

// ---------------- GEMM1 (fp16x3 mma): logits -> mask -> block max -> e_blk ----------------
__global__ void __launch_bounds__(256) k_gemm1_mma(const int* __restrict__ lens32) {
    extern __shared__ char smem[];
    const int bz = blockIdx.z, t0 = blockIdx.y * 128, s0 = blockIdx.x * 128;
    const int len = decode_len(lens32, bz);
    if (s0 >= len) return;   // fully-masked tile: e==0 there by zero-invariant

    float acc[4][4][4];
    tc_loop16(smem,
              g_srchi + (size_t)(bz * TT + t0) * DD, g_srclo + (size_t)(bz * TT + t0) * DD, DD,
              g_mbhi + (size_t)(bz * SS + s0) * DD, g_mblo + (size_t)(bz * SS + s0) * DD, DD,
              DD / CH_K, acc);
    __syncthreads();

    const int tid = threadIdx.x, lane = tid & 31, wid = tid >> 5;
    const int wm = wid >> 2, wn = wid & 3, g = lane >> 2, tg = lane & 3;
    float (*red)[17] = (float(*)[17])smem;

#pragma unroll
    for (int mt = 0; mt < 4; ++mt) {
#pragma unroll
        for (int h = 0; h < 2; ++h) {
            int row = wm * 64 + mt * 16 + h * 8 + g;
            float m = -INFINITY;
#pragma unroll
            for (int nt = 0; nt < 4; ++nt) {
                int sg = s0 + wn * 32 + nt * 8 + tg * 2;
                if (sg < len)     m = fmaxf(m, acc[mt][nt][h * 2 + 0]);
                if (sg + 1 < len) m = fmaxf(m, acc[mt][nt][h * 2 + 1]);
            }
            red[row][wn * 4 + tg] = m;
        }
    }
    __syncthreads();
    if (tid < 128) {
        float m = red[tid][0];
#pragma unroll
        for (int j = 1; j < 16; ++j) m = fmaxf(m, red[tid][j]);
        red[tid][16] = m;
        g_bmax[(size_t)(bz * TT + t0 + tid) * NSBLK + blockIdx.x] = m;
        atomicMax(&g_rowmax[bz * TT + t0 + tid], fenc(m));
    }
    __syncthreads();

#pragma unroll
    for (int mt = 0; mt < 4; ++mt) {
#pragma unroll
        for (int h = 0; h < 2; ++h) {
            int row = wm * 64 + mt * 16 + h * 8 + g;
            float m = red[row][16];
            float* orow = g_align + (size_t)(bz * TT + t0 + row) * SS + s0;
#pragma unroll
            for (int nt = 0; nt < 4; ++nt) {
                int col = wn * 32 + nt * 8 + tg * 2;
                int sg = s0 + col;
                float e0 = (sg < len)     ? __expf(acc[mt][nt][h * 2 + 0] - m) : 0.f;
                float e1 = (sg + 1 < len) ? __expf(acc[mt][nt][h * 2 + 1] - m) : 0.f;
                *(float2*)(orow + col) = make_float2(e0, e1);
            }
        }
    }
}

// ---------------- Phase A: per-chunk column sums of e_blk * f ----------------
__global__ void __launch_bounds__(256) k_colsum(const int* __restrict__ lens32) {
    const int b  = blockIdx.z;
    const int ch = blockIdx.y;
    const int s  = blockIdx.x * 256 + threadIdx.x;
    const int len = decode_len(lens32, b);
    if (blockIdx.x * 256 >= len) {                 // fully-masked CTA
        g_carry[(b * NCHUNK + ch) * SS + s] = 0.f;
        return;
    }
    __shared__ float ffac[TCH][2];
    {
        int tl = threadIdx.x >> 1;
        int sb = threadIdx.x & 1;
        int t  = ch * TCH + tl;
        float mb_ = g_bmax[(size_t)(b * TT + t) * NSBLK + blockIdx.x * 2 + sb];
        float mg  = fdec(g_rowmax[b * TT + t]);
        ffac[tl][sb] = __expf(mb_ - mg);
    }
    __syncthreads();
    const int mysb = threadIdx.x >> 7;
    float sum = 0.f;
    if (s < len) {
        size_t base = (size_t)(b * TT + ch * TCH) * SS + s;
#pragma unroll 4
        for (int r = 0; r < TCH; ++r)
            sum += g_align[base + (size_t)r * SS] * ffac[r][mysb];
    }
    g_carry[(b * NCHUNK + ch) * SS + s] = sum;
}

// ---------------- fused Phase C: prefix + penalty replay + rowsum + normalize ----------------
// One CTA per (chunk, batch) owning ALL of s. u never touches DRAM.
__global__ void __launch_bounds__(256) k_phasec_fused(float* __restrict__ av,
                                                      const int* __restrict__ lens32) {
    __shared__ float ffac[TCH][NSBLK];   // 8 KB
    __shared__ float red[8];
    __shared__ float sinv;

    const int ch = blockIdx.x;
    const int b  = blockIdx.y;
    const int tid = threadIdx.x;
    const int lane = tid & 31, warp = tid >> 5;
    const int len = decode_len(lens32, b);
    const int sbase = tid * 8;
    const bool act = (sbase < len);

    // ffac table: 128 rows x 16 s-blocks; masked blocks -> 0 (guards stale bmax)
    for (int i = tid; i < TCH * NSBLK; i += 256) {
        int r = i >> 4, blk = i & 15;
        int t = ch * TCH + r;
        float v = 0.f;
        if (blk * 128 < len) {
            float mb_ = g_bmax[(size_t)(b * TT + t) * NSBLK + blk];
            float mg  = fdec(g_rowmax[b * TT + t]);
            v = __expf(mb_ - mg);
        }
        ffac[r][blk] = v;
    }

    // chunk-prefix carry (replaces k_scan): P = sum over chunks < ch
    float P[8];
#pragma unroll
    for (int j = 0; j < 8; ++j) P[j] = 0.f;
    for (int c = 0; c < ch; ++c) {
        const float4* cp = (const float4*)(g_carry + (size_t)(b * NCHUNK + c) * SS + sbase);
        float4 c0 = cp[0], c1 = cp[1];
        P[0] += c0.x; P[1] += c0.y; P[2] += c0.z; P[3] += c0.w;
        P[4] += c1.x; P[5] += c1.y; P[6] += c1.z; P[7] += c1.w;
    }
    __syncthreads();

    const int myblk = tid >> 4;
    for (int r = 0; r < TCH; ++r) {
        int t = ch * TCH + r;
        size_t rowoff = (size_t)(b * TT + t) * SS + sbase;
        float e[8];
        if (act) {
            const float4* ep = (const float4*)(g_align + rowoff);
            float4 e0 = ep[0], e1 = ep[1];
            float f = ffac[r][myblk];
            e[0] = e0.x * f; e[1] = e0.y * f; e[2] = e0.z * f; e[3] = e0.w * f;
            e[4] = e1.x * f; e[5] = e1.y * f; e[6] = e1.z * f; e[7] = e1.w * f;
        } else {
#pragma unroll
            for (int j = 0; j < 8; ++j) e[j] = 0.f;
        }
        float u[8];
        float w = 0.f;
#pragma unroll
        for (int j = 0; j < 8; ++j) {
            float pen = (t == 0) ? 1.0f : P[j];
            u[j] = e[j] / (pen + 1e-20f);
            P[j] += e[j];
            w += u[j];
        }
        // deterministic block reduce: warp shfl tree -> 8 slots -> thread 0
        w += __shfl_down_sync(0xffffffffu, w, 16);
        w += __shfl_down_sync(0xffffffffu, w, 8);
        w += __shfl_down_sync(0xffffffffu, w, 4);
        w += __shfl_down_sync(0xffffffffu, w, 2);
        w += __shfl_down_sync(0xffffffffu, w, 1);
        if (lane == 0) red[warp] = w;
        __syncthreads();
        if (tid == 0) {
            float s = 0.f;
#pragma unroll
            for (int j = 0; j < 8; ++j) s += red[j];
            sinv = 1.0f / s;
        }
        __syncthreads();
        float inv = sinv;

        float4* op = (float4*)(av + rowoff);
        op[0] = make_float4(u[0] * inv, u[1] * inv, u[2] * inv, u[3] * inv);
        op[1] = make_float4(u[4] * inv, u[5] * inv, u[6] * inv, u[7] * inv);
        if (act) {
            __half2* hp = (__half2*)(g_avh + rowoff);
            hp[0] = __halves2half2(__float2half_rn(u[0] * inv), __float2half_rn(u[1] * inv));
            hp[1] = __halves2half2(__float2half_rn(u[2] * inv), __float2half_rn(u[3] * inv));
            hp[2] = __halves2half2(__float2half_rn(u[4] * inv), __float2half_rn(u[5] * inv));
            hp[3] = __halves2half2(__float2half_rn(u[6] * inv), __float2half_rn(u[7] * inv));
        }
    }
}

// ---------------- GEMM2 (pure fp16 mma): c = av @ memory_bank, k-loop clipped to len ----------------
__global__ void __launch_bounds__(256) k_gemm2_mma(const int* __restrict__ lens32) {
    extern __shared__ char smem[];
    const int bz = blockIdx.z, t0 = blockIdx.y * 128, n0 = blockIdx.x * 128;
    const int tid = threadIdx.x;
    const int lane = tid & 31, wid = tid >> 5;
    const int wm = wid >> 2, wn = wid & 3, g = lane >> 2, tg = lane & 3;
    uint32_t sb = smem_u32(smem);

    const int len = decode_len(lens32, bz);
    const int nck = (len + CH_K - 1) / CH_K;   // av==0 beyond len (zero-invariant)

    const __half* Ah = g_avh + (size_t)(bz * TT + t0) * SS;
    const __half* Bh = g_mbthi + ((size_t)bz * DD + n0) * SS;

    float acc[4][4][4];
#pragma unroll
    for (int i = 0; i < 4; ++i)
#pragma unroll
        for (int j = 0; j < 4; ++j)
#pragma unroll
            for (int q = 0; q < 4; ++q) acc[i][j][q] = 0.f;

    ld_chunk16(sb, Ah, SS, tid);
    ld_chunk16(sb + TILE_SMEM, Bh, SS, tid);
    cp_commit();

    int buf = 0;
    for (int ck = 0; ck < nck; ++ck) {
        cp_wait0();
        __syncthreads();
        if (ck + 1 < nck) {
            uint32_t nb = sb + (buf ^ 1) * BUF2;
            size_t ko = (size_t)(ck + 1) * CH_K;
            ld_chunk16(nb, Ah + ko, SS, tid);
            ld_chunk16(nb + TILE_SMEM, Bh + ko, SS, tid);
            cp_commit();
        }
        mma_chunk16_1(smem + buf * BUF2, wm, wn, g, tg, acc);
        buf ^= 1;
    }

#pragma unroll
    for (int mt = 0; mt < 4; ++mt) {
#pragma unroll
        for (int h = 0; h < 2; ++h) {
            int row = wm * 64 + mt * 16 + h * 8 + g;
            __half* chrow = g_chi + (size_t)(bz * TT + t0 + row) * DD + n0;
            __half* clrow = g_clo + (size_t)(bz * TT + t0 + row) * DD + n0;
#pragma unroll
            for (int nt = 0; nt < 4; ++nt) {
                int col = wn * 32 + nt * 8 + tg * 2;
                float v0 = acc[mt][nt][h * 2 + 0], v1 = acc[mt][nt][h * 2 + 1];
                __half h0, l0, h1, l1;
                hsplit(v0, h0, l0); hsplit(v1, h1, l1);
                *(__half2*)(chrow + col) = __halves2half2(h0, h1);
                *(__half2*)(clrow + col) = __halves2half2(l0, l1);
            }
        }
    }
}

// ---------------- GEMM3 (fp16x3 mma): attn_h = tanh([c, source] @ W_out) ----------------
__global__ void __launch_bounds__(256) k_gemm3_mma(float* __restrict__ outh) {
    extern __shared__ char smem[];
    const int m0 = blockIdx.y * 128, n0 = blockIdx.x * 128;
    const int tid = threadIdx.x;
    const int lane = tid & 31, wid = tid >> 5;
    const int wm = wid >> 2, wn = wid & 3, g = lane >> 2, tg = lane & 3;
    uint32_t sb = smem_u32(smem);
    const int nck = (2 * DD) / CH_K;   // 8 chunks: 0-3 from c, 4-7 from src

    float acc[4][4][4];
#pragma unroll
    for (int i = 0; i < 4; ++i)
#pragma unroll
        for (int j = 0; j < 4; ++j)
#pragma unroll
            for (int q = 0; q < 4; ++q) acc[i][j][q] = 0.f;

    auto ld_g3 = [&](uint32_t stbase, int ck) {
        const __half *Ah, *Al;
        if (ck < 4) {
            Ah = g_chi + (size_t)m0 * DD + ck * CH_K;
            Al = g_clo + (size_t)m0 * DD + ck * CH_K;
        } else {
            Ah = g_srchi + (size_t)m0 * DD + (ck - 4) * CH_K;
            Al = g_srclo + (size_t)m0 * DD + (ck - 4) * CH_K;
        }
        const __half* Bh = g_wthi + (size_t)n0 * (2 * DD) + ck * CH_K;
        const __half* Bl = g_wtlo + (size_t)n0 * (2 * DD) + ck * CH_K;
        ld_chunk16(stbase + 0 * TILE_SMEM, Ah, DD, tid);
        ld_chunk16(stbase + 1 * TILE_SMEM, Al, DD, tid);
        ld_chunk16(stbase + 2 * TILE_SMEM, Bh, 2 * DD, tid);
        ld_chunk16(stbase + 3 * TILE_SMEM, Bl, 2 * DD, tid);
        cp_commit();
    };

    ld_g3(sb, 0);
    int buf = 0;
    for (int ck = 0; ck < nck; ++ck) {
        cp_wait0();
        __syncthreads();
        if (ck + 1 < nck) ld_g3(sb + (buf ^ 1) * BUF_SZ, ck + 1);
        mma_chunk16(smem + buf * BUF_SZ, wm, wn, g, tg, acc);
        buf ^= 1;
    }

#pragma unroll
    for (int mt = 0; mt < 4; ++mt) {
#pragma unroll
        for (int h = 0; h < 2; ++h) {
            int row = wm * 64 + mt * 16 + h * 8 + g;
            float* orow = outh + (size_t)(m0 + row) * DD + n0;
#pragma unroll
            for (int nt = 0; nt < 4; ++nt) {
                int col = wn * 32 + nt * 8 + tg * 2;
                *(float2*)(orow + col) = make_float2(tanhf(acc[mt][nt][h * 2 + 0]),
                                                     tanhf(acc[mt][nt][h * 2 + 1]));
            }
        }
    }
}

// ---------------- launch ----------------
extern "C" void kernel_launch(void* const* d_in, const int* in_sizes, int n_in,
                              void* d_out, int out_size) {
    const float* src  = (const float*)d_in[0];      // [B,T,D]
    const float* mb   = (const float*)d_in[1];      // [B,S,D]
    const float* W    = (const float*)d_in[2];      // [2D,D]
    const int*   lens = (const int*)d_in[3];        // [B] (int32 or int64; decoded in-kernel)

    float* outh = (float*)d_out;                    // attn_h   [B,T,D]
    float* av   = outh + (size_t)BB * TT * DD;      // align_vectors [B,T,S]

    cudaFuncSetAttribute(k_gemm1_mma, cudaFuncAttributeMaxDynamicSharedMemorySize, GSM_TOTAL);
    cudaFuncSetAttribute(k_gemm2_mma, cudaFuncAttributeMaxDynamicSharedMemorySize, GSM2);
    cudaFuncSetAttribute(k_gemm3_mma, cudaFuncAttributeMaxDynamicSharedMemorySize, GSM_TOTAL);

    __half* srchi; cudaGetSymbolAddress((void**)&srchi, g_srchi);
    __half* srclo; cudaGetSymbolAddress((void**)&srclo, g_srclo);

    k_wsplit<<<dim3((2 * DD) / 32, DD / 32, 1), 256>>>(W);   // + rowmax init
    {
        int n4 = (BB * TT * DD) / 4;
        k_split_h<<<(n4 + 255) / 256, 256>>>((const float4*)src, srchi, srclo, n4);
    }
    k_mbsplit<<<dim3(SS / 32, DD / 32, BB), 256>>>(mb);      // mbhi + mblo + mbthi, one read

    k_gemm1_mma<<<dim3(SS / 128, TT / 128, BB), 256, GSM_TOTAL>>>(lens);

    k_colsum<<<dim3(SS / 256, NCHUNK, BB), 256>>>(lens);
    k_phasec_fused<<<dim3(NCHUNK, BB), 256>>>(av, lens);     // prefix+penalty+rowsum+normalize

    k_gemm2_mma<<<dim3(DD / 128, TT / 128, BB), 256, GSM2>>>(lens);
    k_gemm3_mma<<<dim3(DD / 128, (BB * TT) / 128, 1), 256, GSM_TOTAL>>>(outh);
}

// round 16
// speedup vs baseline: 1.6686x; 1.6686x over previous
#include <cuda_runtime.h>
#include <cuda_fp16.h>
#include <math.h>
#include <stdint.h>

#define BB 8
#define TT 2048
#define SS 2048
#define DD 256
#define NCHUNK 16
#define TCH 128   /* TT / NCHUNK */
#define NSBLK 16  /* SS / 128 */

#define CH_K 64                          /* fp16 elems per k-chunk */
#define PITCH 72                         /* fp16 pitch: bank = 4g+tg, conflict-free */
#define TILE_SMEM (128 * PITCH * 2)      /* 18432 B */
#define BUF_SZ (4 * TILE_SMEM)           /* 73728 B : 4-tile stage (hi/lo A,B) */
#define GSM_TOTAL (2 * BUF_SZ)           /* 147456 B, 2-stage */
#define BUF2 (2 * TILE_SMEM)             /* 36864 B : 2-tile stage (hi-only) */
#define GSM2 (2 * BUF2)                  /* 73728 B -> 2+ CTAs/SM */

// ---------------- scratch (device globals; no runtime allocation) ----------------
// ZERO-INVARIANT: regions with s >= len[b] of g_align / g_avh are NEVER written
// by any kernel, so they stay 0 (module-load zero-init) across all graph replays.
__device__ float        g_align [(size_t)BB * TT * SS]; // e_blk fp32, then u in place
__device__ __half       g_avh   [(size_t)BB * TT * SS]; // fp16 of normalized av
__device__ float        g_bmax  [(size_t)BB * TT * NSBLK];
__device__ unsigned int g_rowmax[BB * TT];
__device__ float        g_carry [BB * NCHUNK * SS];
__device__ float        g_partial[(size_t)BB * TT * 64];
__device__ __half       g_chi   [(size_t)BB * TT * DD]; // context hi/lo fp16
__device__ __half       g_clo   [(size_t)BB * TT * DD];
__device__ __half       g_srchi [(size_t)BB * TT * DD];
__device__ __half       g_srclo [(size_t)BB * TT * DD];
__device__ __half       g_mbhi  [(size_t)BB * SS * DD];
__device__ __half       g_mblo  [(size_t)BB * SS * DD];
__device__ __half       g_mbthi [(size_t)BB * DD * SS]; // transposed [B,D,S], hi only
__device__ __half       g_wthi  [(size_t)DD * 2 * DD];  // W^T [D, 2D] hi/lo
__device__ __half       g_wtlo  [(size_t)DD * 2 * DD];

// ---------------- generic helpers ----------------
__device__ __forceinline__ unsigned fenc(float f) {
    unsigned u = __float_as_uint(f);
    return (u & 0x80000000u) ? ~u : (u | 0x80000000u);
}
__device__ __forceinline__ float fdec(unsigned e) {
    return (e & 0x80000000u) ? __uint_as_float(e ^ 0x80000000u) : __uint_as_float(~e);
}
__device__ __forceinline__ int decode_len(const int* __restrict__ lens32, int b) {
    bool is64 = (lens32[1] == 0) && (lens32[3] == 0) && (lens32[5] == 0) && (lens32[7] == 0);
    if (is64) return (int)((const long long*)lens32)[b];
    return lens32[b];
}
__device__ __forceinline__ void hsplit(float x, __half& h, __half& l) {
    h = __float2half_rn(x);
    l = __float2half_rn(x - __half2float(h));
}
__device__ __forceinline__ uint32_t smem_u32(const void* p) {
    uint32_t a;
    asm("{ .reg .u64 t; cvta.to.shared.u64 t, %1; cvt.u32.u64 %0, t; }" : "=r"(a) : "l"(p));
    return a;
}

// ---------------- cp.async + fp16 mma.sync infra ----------------
__device__ __forceinline__ void cp16(uint32_t dst, const void* src) {
    asm volatile("cp.async.cg.shared.global [%0], [%1], 16;" :: "r"(dst), "l"(src));
}
__device__ __forceinline__ void cp_commit() { asm volatile("cp.async.commit_group;" ::: "memory"); }
__device__ __forceinline__ void cp_wait0()  { asm volatile("cp.async.wait_group 0;" ::: "memory"); }

// one 128-row x 64-fp16 tile (128B/row) into pitched smem
__device__ __forceinline__ void ld_chunk16(uint32_t smbase, const __half* src, size_t stride, int tid) {
    int r0 = tid >> 3, c = tid & 7;
#pragma unroll
    for (int p = 0; p < 4; ++p) {
        int row = r0 + p * 32;
        cp16(smbase + row * (PITCH * 2) + c * 16, src + (size_t)row * stride + c * 8);
    }
}
__device__ __forceinline__ void ld_stage16(uint32_t stbase,
        const __half* Ah, const __half* Al, size_t sA,
        const __half* Bh, const __half* Bl, size_t sB, size_t ko, int tid) {
    ld_chunk16(stbase + 0 * TILE_SMEM, Ah + ko, sA, tid);
    ld_chunk16(stbase + 1 * TILE_SMEM, Al + ko, sA, tid);
    ld_chunk16(stbase + 2 * TILE_SMEM, Bh + ko, sB, tid);
    ld_chunk16(stbase + 3 * TILE_SMEM, Bl + ko, sB, tid);
    cp_commit();
}

__device__ __forceinline__ void mma_f16(float* d, uint32_t a0, uint32_t a1, uint32_t a2, uint32_t a3,
                                        uint32_t b0, uint32_t b1) {
    asm volatile("mma.sync.aligned.m16n8k16.row.col.f32.f16.f16.f32 "
                 "{%0,%1,%2,%3}, {%4,%5,%6,%7}, {%8,%9}, {%0,%1,%2,%3};"
                 : "+f"(d[0]), "+f"(d[1]), "+f"(d[2]), "+f"(d[3])
                 : "r"(a0), "r"(a1), "r"(a2), "r"(a3), "r"(b0), "r"(b1));
}
__device__ __forceinline__ uint32_t hld(const __half* p) { return *(const uint32_t*)p; }

// 3-term chunk (hi/lo A + hi/lo B in one 4-tile stage)
__device__ __forceinline__ void mma_chunk16(const char* stage, int wm, int wn, int g, int tg,
                                            float acc[4][4][4]) {
    const __half* Ash = (const __half*)stage;
    const __half* Asl = Ash + 128 * PITCH;
    const __half* Bsh = Asl + 128 * PITCH;
    const __half* Bsl = Bsh + 128 * PITCH;
#pragma unroll
    for (int ks = 0; ks < 4; ++ks) {
        int k0 = ks * 16;
        uint32_t bh[4][2], bl[4][2];
#pragma unroll
        for (int nt = 0; nt < 4; ++nt) {
            int o = (wn * 32 + nt * 8 + g) * PITCH + k0 + 2 * tg;
            bh[nt][0] = hld(Bsh + o);
            bh[nt][1] = hld(Bsh + o + 8);
            bl[nt][0] = hld(Bsl + o);
            bl[nt][1] = hld(Bsl + o + 8);
        }
#pragma unroll
        for (int mt = 0; mt < 4; ++mt) {
            int o = (wm * 64 + mt * 16 + g) * PITCH + k0 + 2 * tg;
            uint32_t ah0 = hld(Ash + o);
            uint32_t ah1 = hld(Ash + o + 8 * PITCH);
            uint32_t ah2 = hld(Ash + o + 8);
            uint32_t ah3 = hld(Ash + o + 8 * PITCH + 8);
            uint32_t al0 = hld(Asl + o);
            uint32_t al1 = hld(Asl + o + 8 * PITCH);
            uint32_t al2 = hld(Asl + o + 8);
            uint32_t al3 = hld(Asl + o + 8 * PITCH + 8);
#pragma unroll
            for (int nt = 0; nt < 4; ++nt) {
                mma_f16(acc[mt][nt], ah0, ah1, ah2, ah3, bl[nt][0], bl[nt][1]);
                mma_f16(acc[mt][nt], al0, al1, al2, al3, bh[nt][0], bh[nt][1]);
                mma_f16(acc[mt][nt], ah0, ah1, ah2, ah3, bh[nt][0], bh[nt][1]);
            }
        }
    }
}

// 1-term chunk (hi A + hi B in one 2-tile stage)
__device__ __forceinline__ void mma_chunk16_1(const char* stage, int wm, int wn, int g, int tg,
                                              float acc[4][4][4]) {
    const __half* Ash = (const __half*)stage;
    const __half* Bsh = Ash + 128 * PITCH;
#pragma unroll
    for (int ks = 0; ks < 4; ++ks) {
        int k0 = ks * 16;
        uint32_t b[4][2];
#pragma unroll
        for (int nt = 0; nt < 4; ++nt) {
            int o = (wn * 32 + nt * 8 + g) * PITCH + k0 + 2 * tg;
            b[nt][0] = hld(Bsh + o);
            b[nt][1] = hld(Bsh + o + 8);
        }
#pragma unroll
        for (int mt = 0; mt < 4; ++mt) {
            int o = (wm * 64 + mt * 16 + g) * PITCH + k0 + 2 * tg;
            uint32_t a0 = hld(Ash + o);
            uint32_t a1 = hld(Ash + o + 8 * PITCH);
            uint32_t a2 = hld(Ash + o + 8);
            uint32_t a3 = hld(Ash + o + 8 * PITCH + 8);
#pragma unroll
            for (int nt = 0; nt < 4; ++nt)
                mma_f16(acc[mt][nt], a0, a1, a2, a3, b[nt][0], b[nt][1]);
        }
    }
}

// 2-stage pipelined 3-term mainloop
__device__ __forceinline__ void tc_loop16(char* smem,
        const __half* __restrict__ Ah, const __half* __restrict__ Al, size_t sA,
        const __half* __restrict__ Bh, const __half* __restrict__ Bl, size_t sB,
        int nck, float acc[4][4][4]) {
    const int tid = threadIdx.x;
    const int lane = tid & 31, wid = tid >> 5;
    const int wm = wid >> 2, wn = wid & 3;
    const int g = lane >> 2, tg = lane & 3;
    uint32_t sb = smem_u32(smem);

#pragma unroll
    for (int i = 0; i < 4; ++i)
#pragma unroll
        for (int j = 0; j < 4; ++j)
#pragma unroll
            for (int q = 0; q < 4; ++q) acc[i][j][q] = 0.f;

    ld_stage16(sb, Ah, Al, sA, Bh, Bl, sB, 0, tid);

    int buf = 0;
    for (int ck = 0; ck < nck; ++ck) {
        cp_wait0();
        __syncthreads();
        if (ck + 1 < nck)
            ld_stage16(sb + (buf ^ 1) * BUF_SZ, Ah, Al, sA, Bh, Bl, sB, (size_t)(ck + 1) * CH_K, tid);
        mma_chunk16(smem + buf * BUF_SZ, wm, wn, g, tg, acc);
        buf ^= 1;
    }
}

// ---------------- split fp32 -> (fp16 hi, fp16 lo) elementwise (src) ----------------
__global__ void k_split_h(const float4* __restrict__ x, __half* __restrict__ hi,
                          __half* __restrict__ lo, int n4) {
    int i = blockIdx.x * 256 + threadIdx.x;
    if (i >= n4) return;
    float4 v = x[i];
    __half h0, h1, h2, h3, l0, l1, l2, l3;
    hsplit(v.x, h0, l0); hsplit(v.y, h1, l1);
    hsplit(v.z, h2, l2); hsplit(v.w, h3, l3);
    ((__half2*)hi)[2 * i]     = __halves2half2(h0, h1);
    ((__half2*)hi)[2 * i + 1] = __halves2half2(h2, h3);
    ((__half2*)lo)[2 * i]     = __halves2half2(l0, l1);
    ((__half2*)lo)[2 * i + 1] = __halves2half2(l2, l3);
}

// ---------------- single-read mb pipeline: hi/lo row-major + transposed hi ----------------
__global__ void k_mbsplit(const float* __restrict__ mb) {
    __shared__ float tile[32][33];
    int tx = threadIdx.x & 31, ty = threadIdx.x >> 5;
    int s0 = blockIdx.x * 32, d0 = blockIdx.y * 32, b = blockIdx.z;
#pragma unroll
    for (int j = 0; j < 4; ++j) {
        float x = mb[((size_t)b * SS + s0 + ty + j * 8) * DD + d0 + tx];
        tile[ty + j * 8][tx] = x;
        __half h, l;
        hsplit(x, h, l);
        size_t o = ((size_t)b * SS + s0 + ty + j * 8) * DD + d0 + tx;
        g_mbhi[o] = h;
        g_mblo[o] = l;
    }
    __syncthreads();
#pragma unroll
    for (int j = 0; j < 4; ++j) {
        float x = tile[tx][ty + j * 8];
        size_t o = ((size_t)b * DD + d0 + ty + j * 8) * SS + s0 + tx;
        g_mbthi[o] = __float2half_rn(x);
    }
}

// ---------------- W split (+ rowmax init piggyback) ----------------
__global__ void k_wsplit(const float* __restrict__ W) {
    int flat = (blockIdx.y * gridDim.x + blockIdx.x) * 256 + threadIdx.x;
    if (flat < BB * TT) g_rowmax[flat] = 0x007FFFFFu;  // fenc(-inf)

    __shared__ float tile[32][33];
    int tx = threadIdx.x & 31, ty = threadIdx.x >> 5;
    int k0 = blockIdx.x * 32, n0 = blockIdx.y * 32;
#pragma unroll
    for (int j = 0; j < 4; ++j)
        tile[ty + j * 8][tx] = W[(size_t)(k0 + ty + j * 8) * DD + n0 + tx];
    __syncthreads();
#pragma unroll
    for (int j = 0; j < 4; ++j) {
        float x = tile[tx][ty + j * 8];
        __half h, l;
        hsplit(x, h, l);
        size_t o = (size_t)(n0 + ty + j * 8) * (2 * DD) + k0 + tx;
        g_wthi[o] = h;
        g_wtlo[o] = l;
    }
}

// ---------------- GEMM1 (fp16x3 mma): logits -> mask -> block max -> e_blk ----------------
__global__ void __launch_bounds__(256) k_gemm1_mma(const int* __restrict__ lens32) {
    extern __shared__ char smem[];
    const int bz = blockIdx.z, t0 = blockIdx.y * 128, s0 = blockIdx.x * 128;
    const int len = decode_len(lens32, bz);
    if (s0 >= len) return;   // fully-masked tile: e==0 there by zero-invariant

    float acc[4][4][4];
    tc_loop16(smem,
              g_srchi + (size_t)(bz * TT + t0) * DD, g_srclo + (size_t)(bz * TT + t0) * DD, DD,
              g_mbhi + (size_t)(bz * SS + s0) * DD, g_mblo + (size_t)(bz * SS + s0) * DD, DD,
              DD / CH_K, acc);
    __syncthreads();

    const int tid = threadIdx.x, lane = tid & 31, wid = tid >> 5;
    const int wm = wid >> 2, wn = wid & 3, g = lane >> 2, tg = lane & 3;
    float (*red)[17] = (float(*)[17])smem;

#pragma unroll
    for (int mt = 0; mt < 4; ++mt) {
#pragma unroll
        for (int h = 0; h < 2; ++h) {
            int row = wm * 64 + mt * 16 + h * 8 + g;
            float m = -INFINITY;
#pragma unroll
            for (int nt = 0; nt < 4; ++nt) {
                int sg = s0 + wn * 32 + nt * 8 + tg * 2;
                if (sg < len)     m = fmaxf(m, acc[mt][nt][h * 2 + 0]);
                if (sg + 1 < len) m = fmaxf(m, acc[mt][nt][h * 2 + 1]);
            }
            red[row][wn * 4 + tg] = m;
        }
    }
    __syncthreads();
    if (tid < 128) {
        float m = red[tid][0];
#pragma unroll
        for (int j = 1; j < 16; ++j) m = fmaxf(m, red[tid][j]);
        red[tid][16] = m;
        g_bmax[(size_t)(bz * TT + t0 + tid) * NSBLK + blockIdx.x] = m;
        atomicMax(&g_rowmax[bz * TT + t0 + tid], fenc(m));
    }
    __syncthreads();

#pragma unroll
    for (int mt = 0; mt < 4; ++mt) {
#pragma unroll
        for (int h = 0; h < 2; ++h) {
            int row = wm * 64 + mt * 16 + h * 8 + g;
            float m = red[row][16];
            float* orow = g_align + (size_t)(bz * TT + t0 + row) * SS + s0;
#pragma unroll
            for (int nt = 0; nt < 4; ++nt) {
                int col = wn * 32 + nt * 8 + tg * 2;
                int sg = s0 + col;
                float e0 = (sg < len)     ? __expf(acc[mt][nt][h * 2 + 0] - m) : 0.f;
                float e1 = (sg + 1 < len) ? __expf(acc[mt][nt][h * 2 + 1] - m) : 0.f;
                *(float2*)(orow + col) = make_float2(e0, e1);
            }
        }
    }
}

// ---------------- Phase A: per-chunk column sums of e_blk * f ----------------
__global__ void __launch_bounds__(256) k_colsum(const int* __restrict__ lens32) {
    const int b  = blockIdx.z;
    const int ch = blockIdx.y;
    const int s  = blockIdx.x * 256 + threadIdx.x;
    const int len = decode_len(lens32, b);
    if (blockIdx.x * 256 >= len) {                 // fully-masked CTA
        g_carry[(b * NCHUNK + ch) * SS + s] = 0.f;
        return;
    }
    __shared__ float ffac[TCH][2];
    {
        int tl = threadIdx.x >> 1;
        int sb = threadIdx.x & 1;
        int t  = ch * TCH + tl;
        float mb_ = g_bmax[(size_t)(b * TT + t) * NSBLK + blockIdx.x * 2 + sb];
        float mg  = fdec(g_rowmax[b * TT + t]);
        ffac[tl][sb] = __expf(mb_ - mg);
    }
    __syncthreads();
    const int mysb = threadIdx.x >> 7;
    float sum = 0.f;
    if (s < len) {
        size_t base = (size_t)(b * TT + ch * TCH) * SS + s;
#pragma unroll 4
        for (int r = 0; r < TCH; ++r)
            sum += g_align[base + (size_t)r * SS] * ffac[r][mysb];
    }
    g_carry[(b * NCHUNK + ch) * SS + s] = sum;
}

// ---------------- tiny exclusive scan over chunks ----------------
__global__ void k_scan() {
    int i = blockIdx.x * blockDim.x + threadIdx.x;
    if (i >= BB * SS) return;
    int b = i / SS, s = i % SS;
    float run = 0.f;
    for (int c = 0; c < NCHUNK; ++c) {
        int idx = (b * NCHUNK + c) * SS + s;
        float v = g_carry[idx];
        g_carry[idx] = run;
        run += v;
    }
}

// ---------------- Phase C: penalty replay, u (fp32) in place, partial rowsums ----------------
__global__ void __launch_bounds__(256) k_phasec(const int* __restrict__ lens32) {
    const int b  = blockIdx.z;
    const int ch = blockIdx.y;
    const int s  = blockIdx.x * 256 + threadIdx.x;
    const int lane = threadIdx.x & 31;
    const int warp = threadIdx.x >> 5;
    const int len = decode_len(lens32, b);
    if (blockIdx.x * 256 >= len) {                 // fully-masked CTA: zero partials
        for (int i = threadIdx.x; i < TCH * 8; i += 256) {
            int r = i >> 3, w = i & 7;
            g_partial[(size_t)(b * TT + ch * TCH + r) * 64 + blockIdx.x * 8 + w] = 0.f;
        }
        return;
    }
    __shared__ float ffac[TCH][2];
    {
        int tl = threadIdx.x >> 1;
        int sb = threadIdx.x & 1;
        int t  = ch * TCH + tl;
        float mb_ = g_bmax[(size_t)(b * TT + t) * NSBLK + blockIdx.x * 2 + sb];
        float mg  = fdec(g_rowmax[b * TT + t]);
        ffac[tl][sb] = __expf(mb_ - mg);
    }
    __syncthreads();
    const int mysb = threadIdx.x >> 7;
    const bool act = (s < len);

    float P = g_carry[(b * NCHUNK + ch) * SS + s];
    size_t base = (size_t)(b * TT + ch * TCH) * SS + s;
#pragma unroll 2
    for (int r = 0; r < TCH; ++r) {
        int t = ch * TCH + r;
        size_t off = base + (size_t)r * SS;
        float e = act ? (g_align[off] * ffac[r][mysb]) : 0.f;
        float pen = (t == 0) ? 1.0f : P;
        float u = e / (pen + 1e-20f);
        P += e;
        if (act) g_align[off] = u;   // masked region never written (zero-invariant)
        float w = u;
        w += __shfl_down_sync(0xffffffffu, w, 16);
        w += __shfl_down_sync(0xffffffffu, w, 8);
        w += __shfl_down_sync(0xffffffffu, w, 4);
        w += __shfl_down_sync(0xffffffffu, w, 2);
        w += __shfl_down_sync(0xffffffffu, w, 1);
        if (lane == 0) g_partial[(size_t)(b * TT + t) * 64 + blockIdx.x * 8 + warp] = w;
    }
}

// ---------------- normalize: in-CTA rowsum, av = u*inv -> d_out, avh fp16 ----------------
__global__ void __launch_bounds__(256) k_normsplit(float* __restrict__ av,
                                                   const int* __restrict__ lens32) {
    __shared__ float red[64];
    __shared__ float sinv;
    int row = blockIdx.x;
    int b = row / TT;
    const int len = decode_len(lens32, b);
    int t = threadIdx.x;
    if (t < 64) red[t] = g_partial[(size_t)row * 64 + t];
    __syncthreads();
    if (t == 0) {
        float s = 0.f;
#pragma unroll
        for (int j = 0; j < 64; ++j) s += red[j];   // fixed order: deterministic
        sinv = 1.0f / s;
    }
    __syncthreads();
    float inv = sinv;

    const float4* up = (const float4*)(g_align + (size_t)row * SS);
    float4* op = (float4*)(av + (size_t)row * SS);
    __half2* hp = (__half2*)(g_avh + (size_t)row * SS);
#pragma unroll
    for (int q = 0; q < 2; ++q) {
        int i = t + q * 256;
        if (i * 4 >= len) {      // masked: d_out must still be zeroed (poisoned buffer)
            op[i] = make_float4(0.f, 0.f, 0.f, 0.f);
            // avh masked region untouched: zero-invariant (never written anywhere)
        } else {
            float4 u = up[i];    // masked components within are exactly 0
            float4 a = make_float4(u.x * inv, u.y * inv, u.z * inv, u.w * inv);
            op[i] = a;
            hp[2 * i]     = __halves2half2(__float2half_rn(a.x), __float2half_rn(a.y));
            hp[2 * i + 1] = __halves2half2(__float2half_rn(a.z), __float2half_rn(a.w));
        }
    }
}

// ---------------- GEMM2 (pure fp16 mma): c = av @ memory_bank, k-loop clipped to len ----------------
__global__ void __launch_bounds__(256) k_gemm2_mma(const int* __restrict__ lens32) {
    extern __shared__ char smem[];
    const int bz = blockIdx.z, t0 = blockIdx.y * 128, n0 = blockIdx.x * 128;
    const int tid = threadIdx.x;
    const int lane = tid & 31, wid = tid >> 5;
    const int wm = wid >> 2, wn = wid & 3, g = lane >> 2, tg = lane & 3;
    uint32_t sb = smem_u32(smem);

    const int len = decode_len(lens32, bz);
    const int nck = (len + CH_K - 1) / CH_K;   // av==0 beyond len (zero-invariant)

    const __half* Ah = g_avh + (size_t)(bz * TT + t0) * SS;
    const __half* Bh = g_mbthi + ((size_t)bz * DD + n0) * SS;

    float acc[4][4][4];
#pragma unroll
    for (int i = 0; i < 4; ++i)
#pragma unroll
        for (int j = 0; j < 4; ++j)
#pragma unroll
            for (int q = 0; q < 4; ++q) acc[i][j][q] = 0.f;

    ld_chunk16(sb, Ah, SS, tid);
    ld_chunk16(sb + TILE_SMEM, Bh, SS, tid);
    cp_commit();

    int buf = 0;
    for (int ck = 0; ck < nck; ++ck) {
        cp_wait0();
        __syncthreads();
        if (ck + 1 < nck) {
            uint32_t nb = sb + (buf ^ 1) * BUF2;
            size_t ko = (size_t)(ck + 1) * CH_K;
            ld_chunk16(nb, Ah + ko, SS, tid);
            ld_chunk16(nb + TILE_SMEM, Bh + ko, SS, tid);
            cp_commit();
        }
        mma_chunk16_1(smem + buf * BUF2, wm, wn, g, tg, acc);
        buf ^= 1;
    }

#pragma unroll
    for (int mt = 0; mt < 4; ++mt) {
#pragma unroll
        for (int h = 0; h < 2; ++h) {
            int row = wm * 64 + mt * 16 + h * 8 + g;
            __half* chrow = g_chi + (size_t)(bz * TT + t0 + row) * DD + n0;
            __half* clrow = g_clo + (size_t)(bz * TT + t0 + row) * DD + n0;
#pragma unroll
            for (int nt = 0; nt < 4; ++nt) {
                int col = wn * 32 + nt * 8 + tg * 2;
                float v0 = acc[mt][nt][h * 2 + 0], v1 = acc[mt][nt][h * 2 + 1];
                __half h0, l0, h1, l1;
                hsplit(v0, h0, l0); hsplit(v1, h1, l1);
                *(__half2*)(chrow + col) = __halves2half2(h0, h1);
                *(__half2*)(clrow + col) = __halves2half2(l0, l1);
            }
        }
    }
}

// ---------------- GEMM3 (fp16x3 mma): attn_h = tanh([c, source] @ W_out) ----------------
__global__ void __launch_bounds__(256) k_gemm3_mma(float* __restrict__ outh) {
    extern __shared__ char smem[];
    const int m0 = blockIdx.y * 128, n0 = blockIdx.x * 128;
    const int tid = threadIdx.x;
    const int lane = tid & 31, wid = tid >> 5;
    const int wm = wid >> 2, wn = wid & 3, g = lane >> 2, tg = lane & 3;
    uint32_t sb = smem_u32(smem);
    const int nck = (2 * DD) / CH_K;   // 8 chunks: 0-3 from c, 4-7 from src

    float acc[4][4][4];
#pragma unroll
    for (int i = 0; i < 4; ++i)
#pragma unroll
        for (int j = 0; j < 4; ++j)
#pragma unroll
            for (int q = 0; q < 4; ++q) acc[i][j][q] = 0.f;

    auto ld_g3 = [&](uint32_t stbase, int ck) {
        const __half *Ah, *Al;
        if (ck < 4) {
            Ah = g_chi + (size_t)m0 * DD + ck * CH_K;
            Al = g_clo + (size_t)m0 * DD + ck * CH_K;
        } else {
            Ah = g_srchi + (size_t)m0 * DD + (ck - 4) * CH_K;
            Al = g_srclo + (size_t)m0 * DD + (ck - 4) * CH_K;
        }
        const __half* Bh = g_wthi + (size_t)n0 * (2 * DD) + ck * CH_K;
        const __half* Bl = g_wtlo + (size_t)n0 * (2 * DD) + ck * CH_K;
        ld_chunk16(stbase + 0 * TILE_SMEM, Ah, DD, tid);
        ld_chunk16(stbase + 1 * TILE_SMEM, Al, DD, tid);
        ld_chunk16(stbase + 2 * TILE_SMEM, Bh, 2 * DD, tid);
        ld_chunk16(stbase + 3 * TILE_SMEM, Bl, 2 * DD, tid);
        cp_commit();
    };

    ld_g3(sb, 0);
    int buf = 0;
    for (int ck = 0; ck < nck; ++ck) {
        cp_wait0();
        __syncthreads();
        if (ck + 1 < nck) ld_g3(sb + (buf ^ 1) * BUF_SZ, ck + 1);
        mma_chunk16(smem + buf * BUF_SZ, wm, wn, g, tg, acc);
        buf ^= 1;
    }

#pragma unroll
    for (int mt = 0; mt < 4; ++mt) {
#pragma unroll
        for (int h = 0; h < 2; ++h) {
            int row = wm * 64 + mt * 16 + h * 8 + g;
            float* orow = outh + (size_t)(m0 + row) * DD + n0;
#pragma unroll
            for (int nt = 0; nt < 4; ++nt) {
                int col = wn * 32 + nt * 8 + tg * 2;
                *(float2*)(orow + col) = make_float2(tanhf(acc[mt][nt][h * 2 + 0]),
                                                     tanhf(acc[mt][nt][h * 2 + 1]));
            }
        }
    }
}

// ---------------- launch ----------------
extern "C" void kernel_launch(void* const* d_in, const int* in_sizes, int n_in,
                              void* d_out, int out_size) {
    const float* src  = (const float*)d_in[0];      // [B,T,D]
    const float* mb   = (const float*)d_in[1];      // [B,S,D]
    const float* W    = (const float*)d_in[2];      // [2D,D]
    const int*   lens = (const int*)d_in[3];        // [B] (int32 or int64; decoded in-kernel)

    float* outh = (float*)d_out;                    // attn_h   [B,T,D]
    float* av   = outh + (size_t)BB * TT * DD;      // align_vectors [B,T,S]

    cudaFuncSetAttribute(k_gemm1_mma, cudaFuncAttributeMaxDynamicSharedMemorySize, GSM_TOTAL);
    cudaFuncSetAttribute(k_gemm2_mma, cudaFuncAttributeMaxDynamicSharedMemorySize, GSM2);
    cudaFuncSetAttribute(k_gemm3_mma, cudaFuncAttributeMaxDynamicSharedMemorySize, GSM_TOTAL);

    __half* srchi; cudaGetSymbolAddress((void**)&srchi, g_srchi);
    __half* srclo; cudaGetSymbolAddress((void**)&srclo, g_srclo);

    k_wsplit<<<dim3((2 * DD) / 32, DD / 32, 1), 256>>>(W);   // + rowmax init
    {
        int n4 = (BB * TT * DD) / 4;
        k_split_h<<<(n4 + 255) / 256, 256>>>((const float4*)src, srchi, srclo, n4);
    }
    k_mbsplit<<<dim3(SS / 32, DD / 32, BB), 256>>>(mb);      // mbhi + mblo + mbthi, one read

    k_gemm1_mma<<<dim3(SS / 128, TT / 128, BB), 256, GSM_TOTAL>>>(lens);

    k_colsum<<<dim3(SS / 256, NCHUNK, BB), 256>>>(lens);
    k_scan<<<(BB * SS + 255) / 256, 256>>>();
    k_phasec<<<dim3(SS / 256, NCHUNK, BB), 256>>>(lens);
    k_normsplit<<<BB * TT, 256>>>(av, lens);                  // in-CTA rowsum fused

    k_gemm2_mma<<<dim3(DD / 128, TT / 128, BB), 256, GSM2>>>(lens);
    k_gemm3_mma<<<dim3(DD / 128, (BB * TT) / 128, 1), 256, GSM_TOTAL>>>(outh);
}

// round 17
// speedup vs baseline: 1.7443x; 1.0454x over previous
#include <cuda_runtime.h>
#include <cuda_fp16.h>
#include <math.h>
#include <stdint.h>

#define BB 8
#define TT 2048
#define SS 2048
#define DD 256
#define NCHUNK 16
#define TCH 128   /* TT / NCHUNK */
#define NSBLK 16  /* SS / 128 */

#define CH_K 64                          /* fp16 elems per k-chunk */
#define PITCH 72                         /* fp16 pitch: bank = 4g+tg, conflict-free */
#define TILE_SMEM (128 * PITCH * 2)      /* 18432 B */
#define BUF_SZ (4 * TILE_SMEM)           /* 73728 B : 4-tile stage (hi/lo A,B) */
#define GSM_TOTAL (2 * BUF_SZ)           /* 147456 B, 2-stage */
#define BUF2 (2 * TILE_SMEM)             /* 36864 B : 2-tile stage (hi-only) */
#define GSM2 (2 * BUF2)                  /* 73728 B -> 2+ CTAs/SM */

// ---------------- scratch (device globals; no runtime allocation) ----------------
// ZERO-INVARIANT: regions with s >= len[b] of g_align / g_avh are NEVER written
// by any kernel, so they stay 0 (module-load zero-init) across all graph replays.
__device__ float        g_align [(size_t)BB * TT * SS]; // e_blk fp32, then u in place
__device__ __half       g_avh   [(size_t)BB * TT * SS]; // fp16 of normalized av
__device__ float        g_bmax  [(size_t)BB * TT * NSBLK];
__device__ unsigned int g_rowmax[BB * TT];
__device__ float        g_carry [BB * NCHUNK * SS];
__device__ float        g_partial[(size_t)BB * TT * 64];
__device__ __half       g_chi   [(size_t)BB * TT * DD]; // context fp16 (single term)
__device__ __half       g_srchi [(size_t)BB * TT * DD];
__device__ __half       g_srclo [(size_t)BB * TT * DD];
__device__ __half       g_mbhi  [(size_t)BB * SS * DD];
__device__ __half       g_mblo  [(size_t)BB * SS * DD];
__device__ __half       g_mbthi [(size_t)BB * DD * SS]; // transposed [B,D,S], hi only
__device__ __half       g_wthi  [(size_t)DD * 2 * DD];  // W^T [D, 2D] hi/lo
__device__ __half       g_wtlo  [(size_t)DD * 2 * DD];

// ---------------- generic helpers ----------------
__device__ __forceinline__ unsigned fenc(float f) {
    unsigned u = __float_as_uint(f);
    return (u & 0x80000000u) ? ~u : (u | 0x80000000u);
}
__device__ __forceinline__ float fdec(unsigned e) {
    return (e & 0x80000000u) ? __uint_as_float(e ^ 0x80000000u) : __uint_as_float(~e);
}
__device__ __forceinline__ int decode_len(const int* __restrict__ lens32, int b) {
    bool is64 = (lens32[1] == 0) && (lens32[3] == 0) && (lens32[5] == 0) && (lens32[7] == 0);
    if (is64) return (int)((const long long*)lens32)[b];
    return lens32[b];
}
__device__ __forceinline__ void hsplit(float x, __half& h, __half& l) {
    h = __float2half_rn(x);
    l = __float2half_rn(x - __half2float(h));
}
__device__ __forceinline__ uint32_t smem_u32(const void* p) {
    uint32_t a;
    asm("{ .reg .u64 t; cvta.to.shared.u64 t, %1; cvt.u32.u64 %0, t; }" : "=r"(a) : "l"(p));
    return a;
}

// ---------------- cp.async + fp16 mma.sync infra ----------------
__device__ __forceinline__ void cp16(uint32_t dst, const void* src) {
    asm volatile("cp.async.cg.shared.global [%0], [%1], 16;" :: "r"(dst), "l"(src));
}
__device__ __forceinline__ void cp_commit() { asm volatile("cp.async.commit_group;" ::: "memory"); }
__device__ __forceinline__ void cp_wait0()  { asm volatile("cp.async.wait_group 0;" ::: "memory"); }

// one 128-row x 64-fp16 tile (128B/row) into pitched smem
__device__ __forceinline__ void ld_chunk16(uint32_t smbase, const __half* src, size_t stride, int tid) {
    int r0 = tid >> 3, c = tid & 7;
#pragma unroll
    for (int p = 0; p < 4; ++p) {
        int row = r0 + p * 32;
        cp16(smbase + row * (PITCH * 2) + c * 16, src + (size_t)row * stride + c * 8);
    }
}
__device__ __forceinline__ void ld_stage16(uint32_t stbase,
        const __half* Ah, const __half* Al, size_t sA,
        const __half* Bh, const __half* Bl, size_t sB, size_t ko, int tid) {
    ld_chunk16(stbase + 0 * TILE_SMEM, Ah + ko, sA, tid);
    ld_chunk16(stbase + 1 * TILE_SMEM, Al + ko, sA, tid);
    ld_chunk16(stbase + 2 * TILE_SMEM, Bh + ko, sB, tid);
    ld_chunk16(stbase + 3 * TILE_SMEM, Bl + ko, sB, tid);
    cp_commit();
}

__device__ __forceinline__ void mma_f16(float* d, uint32_t a0, uint32_t a1, uint32_t a2, uint32_t a3,
                                        uint32_t b0, uint32_t b1) {
    asm volatile("mma.sync.aligned.m16n8k16.row.col.f32.f16.f16.f32 "
                 "{%0,%1,%2,%3}, {%4,%5,%6,%7}, {%8,%9}, {%0,%1,%2,%3};"
                 : "+f"(d[0]), "+f"(d[1]), "+f"(d[2]), "+f"(d[3])
                 : "r"(a0), "r"(a1), "r"(a2), "r"(a3), "r"(b0), "r"(b1));
}
__device__ __forceinline__ uint32_t hld(const __half* p) { return *(const uint32_t*)p; }

// 3-term chunk (hi/lo A + hi/lo B in one 4-tile stage)
__device__ __forceinline__ void mma_chunk16(const char* stage, int wm, int wn, int g, int tg,
                                            float acc[4][4][4]) {
    const __half* Ash = (const __half*)stage;
    const __half* Asl = Ash + 128 * PITCH;
    const __half* Bsh = Asl + 128 * PITCH;
    const __half* Bsl = Bsh + 128 * PITCH;
#pragma unroll
    for (int ks = 0; ks < 4; ++ks) {
        int k0 = ks * 16;
        uint32_t bh[4][2], bl[4][2];
#pragma unroll
        for (int nt = 0; nt < 4; ++nt) {
            int o = (wn * 32 + nt * 8 + g) * PITCH + k0 + 2 * tg;
            bh[nt][0] = hld(Bsh + o);
            bh[nt][1] = hld(Bsh + o + 8);
            bl[nt][0] = hld(Bsl + o);
            bl[nt][1] = hld(Bsl + o + 8);
        }
#pragma unroll
        for (int mt = 0; mt < 4; ++mt) {
            int o = (wm * 64 + mt * 16 + g) * PITCH + k0 + 2 * tg;
            uint32_t ah0 = hld(Ash + o);
            uint32_t ah1 = hld(Ash + o + 8 * PITCH);
            uint32_t ah2 = hld(Ash + o + 8);
            uint32_t ah3 = hld(Ash + o + 8 * PITCH + 8);
            uint32_t al0 = hld(Asl + o);
            uint32_t al1 = hld(Asl + o + 8 * PITCH);
            uint32_t al2 = hld(Asl + o + 8);
            uint32_t al3 = hld(Asl + o + 8 * PITCH + 8);
#pragma unroll
            for (int nt = 0; nt < 4; ++nt) {
                mma_f16(acc[mt][nt], ah0, ah1, ah2, ah3, bl[nt][0], bl[nt][1]);
                mma_f16(acc[mt][nt], al0, al1, al2, al3, bh[nt][0], bh[nt][1]);
                mma_f16(acc[mt][nt], ah0, ah1, ah2, ah3, bh[nt][0], bh[nt][1]);
            }
        }
    }
}

// 2-term chunk (A hi only vs B hi+lo; A tile0, B tiles 2,3 of a 4-tile stage)
__device__ __forceinline__ void mma_chunk16_2(const char* stage, int wm, int wn, int g, int tg,
                                              float acc[4][4][4]) {
    const __half* Ash = (const __half*)stage;
    const __half* Bsh = Ash + 2 * 128 * PITCH;
    const __half* Bsl = Ash + 3 * 128 * PITCH;
#pragma unroll
    for (int ks = 0; ks < 4; ++ks) {
        int k0 = ks * 16;
        uint32_t bh[4][2], bl[4][2];
#pragma unroll
        for (int nt = 0; nt < 4; ++nt) {
            int o = (wn * 32 + nt * 8 + g) * PITCH + k0 + 2 * tg;
            bh[nt][0] = hld(Bsh + o);
            bh[nt][1] = hld(Bsh + o + 8);
            bl[nt][0] = hld(Bsl + o);
            bl[nt][1] = hld(Bsl + o + 8);
        }
#pragma unroll
        for (int mt = 0; mt < 4; ++mt) {
            int o = (wm * 64 + mt * 16 + g) * PITCH + k0 + 2 * tg;
            uint32_t a0 = hld(Ash + o);
            uint32_t a1 = hld(Ash + o + 8 * PITCH);
            uint32_t a2 = hld(Ash + o + 8);
            uint32_t a3 = hld(Ash + o + 8 * PITCH + 8);
#pragma unroll
            for (int nt = 0; nt < 4; ++nt) {
                mma_f16(acc[mt][nt], a0, a1, a2, a3, bl[nt][0], bl[nt][1]);
                mma_f16(acc[mt][nt], a0, a1, a2, a3, bh[nt][0], bh[nt][1]);
            }
        }
    }
}

// 1-term chunk (hi A + hi B in one 2-tile stage)
__device__ __forceinline__ void mma_chunk16_1(const char* stage, int wm, int wn, int g, int tg,
                                              float acc[4][4][4]) {
    const __half* Ash = (const __half*)stage;
    const __half* Bsh = Ash + 128 * PITCH;
#pragma unroll
    for (int ks = 0; ks < 4; ++ks) {
        int k0 = ks * 16;
        uint32_t b[4][2];
#pragma unroll
        for (int nt = 0; nt < 4; ++nt) {
            int o = (wn * 32 + nt * 8 + g) * PITCH + k0 + 2 * tg;
            b[nt][0] = hld(Bsh + o);
            b[nt][1] = hld(Bsh + o + 8);
        }
#pragma unroll
        for (int mt = 0; mt < 4; ++mt) {
            int o = (wm * 64 + mt * 16 + g) * PITCH + k0 + 2 * tg;
            uint32_t a0 = hld(Ash + o);
            uint32_t a1 = hld(Ash + o + 8 * PITCH);
            uint32_t a2 = hld(Ash + o + 8);
            uint32_t a3 = hld(Ash + o + 8 * PITCH + 8);
#pragma unroll
            for (int nt = 0; nt < 4; ++nt)
                mma_f16(acc[mt][nt], a0, a1, a2, a3, b[nt][0], b[nt][1]);
        }
    }
}

// 2-stage pipelined 3-term mainloop
__device__ __forceinline__ void tc_loop16(char* smem,
        const __half* __restrict__ Ah, const __half* __restrict__ Al, size_t sA,
        const __half* __restrict__ Bh, const __half* __restrict__ Bl, size_t sB,
        int nck, float acc[4][4][4]) {
    const int tid = threadIdx.x;
    const int lane = tid & 31, wid = tid >> 5;
    const int wm = wid >> 2, wn = wid & 3;
    const int g = lane >> 2, tg = lane & 3;
    uint32_t sb = smem_u32(smem);

#pragma unroll
    for (int i = 0; i < 4; ++i)
#pragma unroll
        for (int j = 0; j < 4; ++j)
#pragma unroll
            for (int q = 0; q < 4; ++q) acc[i][j][q] = 0.f;

    ld_stage16(sb, Ah, Al, sA, Bh, Bl, sB, 0, tid);

    int buf = 0;
    for (int ck = 0; ck < nck; ++ck) {
        cp_wait0();
        __syncthreads();
        if (ck + 1 < nck)
            ld_stage16(sb + (buf ^ 1) * BUF_SZ, Ah, Al, sA, Bh, Bl, sB, (size_t)(ck + 1) * CH_K, tid);
        mma_chunk16(smem + buf * BUF_SZ, wm, wn, g, tg, acc);
        buf ^= 1;
    }
}

// ---------------- split fp32 -> (fp16 hi, fp16 lo) elementwise (src) ----------------
__global__ void k_split_h(const float4* __restrict__ x, __half* __restrict__ hi,
                          __half* __restrict__ lo, int n4) {
    int i = blockIdx.x * 256 + threadIdx.x;
    if (i >= n4) return;
    float4 v = x[i];
    __half h0, h1, h2, h3, l0, l1, l2, l3;
    hsplit(v.x, h0, l0); hsplit(v.y, h1, l1);
    hsplit(v.z, h2, l2); hsplit(v.w, h3, l3);
    ((__half2*)hi)[2 * i]     = __halves2half2(h0, h1);
    ((__half2*)hi)[2 * i + 1] = __halves2half2(h2, h3);
    ((__half2*)lo)[2 * i]     = __halves2half2(l0, l1);
    ((__half2*)lo)[2 * i + 1] = __halves2half2(l2, l3);
}

// ---------------- single-read mb pipeline: hi/lo row-major + transposed hi ----------------
__global__ void k_mbsplit(const float* __restrict__ mb) {
    __shared__ float tile[32][33];
    int tx = threadIdx.x & 31, ty = threadIdx.x >> 5;
    int s0 = blockIdx.x * 32, d0 = blockIdx.y * 32, b = blockIdx.z;
#pragma unroll
    for (int j = 0; j < 4; ++j) {
        float x = mb[((size_t)b * SS + s0 + ty + j * 8) * DD + d0 + tx];
        tile[ty + j * 8][tx] = x;
        __half h, l;
        hsplit(x, h, l);
        size_t o = ((size_t)b * SS + s0 + ty + j * 8) * DD + d0 + tx;
        g_mbhi[o] = h;
        g_mblo[o] = l;
    }
    __syncthreads();
#pragma unroll
    for (int j = 0; j < 4; ++j) {
        float x = tile[tx][ty + j * 8];
        size_t o = ((size_t)b * DD + d0 + ty + j * 8) * SS + s0 + tx;
        g_mbthi[o] = __float2half_rn(x);
    }
}

// ---------------- W split (+ rowmax init piggyback) ----------------
__global__ void k_wsplit(const float* __restrict__ W) {
    int flat = (blockIdx.y * gridDim.x + blockIdx.x) * 256 + threadIdx.x;
    if (flat < BB * TT) g_rowmax[flat] = 0x007FFFFFu;  // fenc(-inf)

    __shared__ float tile[32][33];
    int tx = threadIdx.x & 31, ty = threadIdx.x >> 5;
    int k0 = blockIdx.x * 32, n0 = blockIdx.y * 32;
#pragma unroll
    for (int j = 0; j < 4; ++j)
        tile[ty + j * 8][tx] = W[(size_t)(k0 + ty + j * 8) * DD + n0 + tx];
    __syncthreads();
#pragma unroll
    for (int j = 0; j < 4; ++j) {
        float x = tile[tx][ty + j * 8];
        __half h, l;
        hsplit(x, h, l);
        size_t o = (size_t)(n0 + ty + j * 8) * (2 * DD) + k0 + tx;
        g_wthi[o] = h;
        g_wtlo[o] = l;
    }
}

// ---------------- GEMM1 (fp16x3 mma): logits -> mask -> block max -> e_blk ----------------
__global__ void __launch_bounds__(256) k_gemm1_mma(const int* __restrict__ lens32) {
    extern __shared__ char smem[];
    const int bz = blockIdx.z, t0 = blockIdx.y * 128, s0 = blockIdx.x * 128;
    const int len = decode_len(lens32, bz);
    if (s0 >= len) return;   // fully-masked tile: e==0 there by zero-invariant

    float acc[4][4][4];
    tc_loop16(smem,
              g_srchi + (size_t)(bz * TT + t0) * DD, g_srclo + (size_t)(bz * TT + t0) * DD, DD,
              g_mbhi + (size_t)(bz * SS + s0) * DD, g_mblo + (size_t)(bz * SS + s0) * DD, DD,
              DD / CH_K, acc);
    __syncthreads();

    const int tid = threadIdx.x, lane = tid & 31, wid = tid >> 5;
    const int wm = wid >> 2, wn = wid & 3, g = lane >> 2, tg = lane & 3;
    float (*red)[17] = (float(*)[17])smem;

#pragma unroll
    for (int mt = 0; mt < 4; ++mt) {
#pragma unroll
        for (int h = 0; h < 2; ++h) {
            int row = wm * 64 + mt * 16 + h * 8 + g;
            float m = -INFINITY;
#pragma unroll
            for (int nt = 0; nt < 4; ++nt) {
                int sg = s0 + wn * 32 + nt * 8 + tg * 2;
                if (sg < len)     m = fmaxf(m, acc[mt][nt][h * 2 + 0]);
                if (sg + 1 < len) m = fmaxf(m, acc[mt][nt][h * 2 + 1]);
            }
            red[row][wn * 4 + tg] = m;
        }
    }
    __syncthreads();
    if (tid < 128) {
        float m = red[tid][0];
#pragma unroll
        for (int j = 1; j < 16; ++j) m = fmaxf(m, red[tid][j]);
        red[tid][16] = m;
        g_bmax[(size_t)(bz * TT + t0 + tid) * NSBLK + blockIdx.x] = m;
        atomicMax(&g_rowmax[bz * TT + t0 + tid], fenc(m));
    }
    __syncthreads();

#pragma unroll
    for (int mt = 0; mt < 4; ++mt) {
#pragma unroll
        for (int h = 0; h < 2; ++h) {
            int row = wm * 64 + mt * 16 + h * 8 + g;
            float m = red[row][16];
            float* orow = g_align + (size_t)(bz * TT + t0 + row) * SS + s0;
#pragma unroll
            for (int nt = 0; nt < 4; ++nt) {
                int col = wn * 32 + nt * 8 + tg * 2;
                int sg = s0 + col;
                float e0 = (sg < len)     ? __expf(acc[mt][nt][h * 2 + 0] - m) : 0.f;
                float e1 = (sg + 1 < len) ? __expf(acc[mt][nt][h * 2 + 1] - m) : 0.f;
                *(float2*)(orow + col) = make_float2(e0, e1);
            }
        }
    }
}

// ---------------- Phase A: per-chunk column sums of e_blk * f ----------------
__global__ void __launch_bounds__(256) k_colsum(const int* __restrict__ lens32) {
    const int b  = blockIdx.z;
    const int ch = blockIdx.y;
    const int s  = blockIdx.x * 256 + threadIdx.x;
    const int len = decode_len(lens32, b);
    if (blockIdx.x * 256 >= len) {                 // fully-masked CTA
        g_carry[(b * NCHUNK + ch) * SS + s] = 0.f;
        return;
    }
    __shared__ float ffac[TCH][2];
    {
        int tl = threadIdx.x >> 1;
        int sb = threadIdx.x & 1;
        int t  = ch * TCH + tl;
        float mb_ = g_bmax[(size_t)(b * TT + t) * NSBLK + blockIdx.x * 2 + sb];
        float mg  = fdec(g_rowmax[b * TT + t]);
        ffac[tl][sb] = __expf(mb_ - mg);
    }
    __syncthreads();
    const int mysb = threadIdx.x >> 7;
    float sum = 0.f;
    if (s < len) {
        size_t base = (size_t)(b * TT + ch * TCH) * SS + s;
#pragma unroll 4
        for (int r = 0; r < TCH; ++r)
            sum += g_align[base + (size_t)r * SS] * ffac[r][mysb];
    }
    g_carry[(b * NCHUNK + ch) * SS + s] = sum;
}

// ---------------- tiny exclusive scan over chunks ----------------
__global__ void k_scan() {
    int i = blockIdx.x * blockDim.x + threadIdx.x;
    if (i >= BB * SS) return;
    int b = i / SS, s = i % SS;
    float run = 0.f;
    for (int c = 0; c < NCHUNK; ++c) {
        int idx = (b * NCHUNK + c) * SS + s;
        float v = g_carry[idx];
        g_carry[idx] = run;
        run += v;
    }
}

// ---------------- Phase C: penalty replay, u (fp32) in place, partial rowsums ----------------
__global__ void __launch_bounds__(256) k_phasec(const int* __restrict__ lens32) {
    const int b  = blockIdx.z;
    const int ch = blockIdx.y;
    const int s  = blockIdx.x * 256 + threadIdx.x;
    const int lane = threadIdx.x & 31;
    const int warp = threadIdx.x >> 5;
    const int len = decode_len(lens32, b);
    if (blockIdx.x * 256 >= len) {                 // fully-masked CTA: zero partials
        for (int i = threadIdx.x; i < TCH * 8; i += 256) {
            int r = i >> 3, w = i & 7;
            g_partial[(size_t)(b * TT + ch * TCH + r) * 64 + blockIdx.x * 8 + w] = 0.f;
        }
        return;
    }
    __shared__ float ffac[TCH][2];
    {
        int tl = threadIdx.x >> 1;
        int sb = threadIdx.x & 1;
        int t  = ch * TCH + tl;
        float mb_ = g_bmax[(size_t)(b * TT + t) * NSBLK + blockIdx.x * 2 + sb];
        float mg  = fdec(g_rowmax[b * TT + t]);
        ffac[tl][sb] = __expf(mb_ - mg);
    }
    __syncthreads();
    const int mysb = threadIdx.x >> 7;
    const bool act = (s < len);

    float P = g_carry[(b * NCHUNK + ch) * SS + s];
    size_t base = (size_t)(b * TT + ch * TCH) * SS + s;
#pragma unroll 2
    for (int r = 0; r < TCH; ++r) {
        int t = ch * TCH + r;
        size_t off = base + (size_t)r * SS;
        float e = act ? (g_align[off] * ffac[r][mysb]) : 0.f;
        float pen = (t == 0) ? 1.0f : P;
        float u = e / (pen + 1e-20f);
        P += e;
        if (act) g_align[off] = u;   // masked region never written (zero-invariant)
        float w = u;
        w += __shfl_down_sync(0xffffffffu, w, 16);
        w += __shfl_down_sync(0xffffffffu, w, 8);
        w += __shfl_down_sync(0xffffffffu, w, 4);
        w += __shfl_down_sync(0xffffffffu, w, 2);
        w += __shfl_down_sync(0xffffffffu, w, 1);
        if (lane == 0) g_partial[(size_t)(b * TT + t) * 64 + blockIdx.x * 8 + warp] = w;
    }
}

// ---------------- normalize: in-CTA rowsum, av = u*inv -> d_out, avh fp16 ----------------
__global__ void __launch_bounds__(256) k_normsplit(float* __restrict__ av,
                                                   const int* __restrict__ lens32) {
    __shared__ float red[64];
    __shared__ float sinv;
    int row = blockIdx.x;
    int b = row / TT;
    const int len = decode_len(lens32, b);
    int t = threadIdx.x;
    if (t < 64) red[t] = g_partial[(size_t)row * 64 + t];
    __syncthreads();
    if (t == 0) {
        float s = 0.f;
#pragma unroll
        for (int j = 0; j < 64; ++j) s += red[j];   // fixed order: deterministic
        sinv = 1.0f / s;
    }
    __syncthreads();
    float inv = sinv;

    const float4* up = (const float4*)(g_align + (size_t)row * SS);
    float4* op = (float4*)(av + (size_t)row * SS);
    __half2* hp = (__half2*)(g_avh + (size_t)row * SS);
#pragma unroll
    for (int q = 0; q < 2; ++q) {
        int i = t + q * 256;
        if (i * 4 >= len) {      // masked: d_out must still be zeroed (poisoned buffer)
            op[i] = make_float4(0.f, 0.f, 0.f, 0.f);
            // avh masked region untouched: zero-invariant (never written anywhere)
        } else {
            float4 u = up[i];    // masked components within are exactly 0
            float4 a = make_float4(u.x * inv, u.y * inv, u.z * inv, u.w * inv);
            op[i] = a;
            hp[2 * i]     = __halves2half2(__float2half_rn(a.x), __float2half_rn(a.y));
            hp[2 * i + 1] = __halves2half2(__float2half_rn(a.z), __float2half_rn(a.w));
        }
    }
}

// ---------------- GEMM2 (pure fp16 mma): c = av @ memory_bank, k-loop clipped to len ----------------
__global__ void __launch_bounds__(256) k_gemm2_mma(const int* __restrict__ lens32) {
    extern __shared__ char smem[];
    const int bz = blockIdx.z, t0 = blockIdx.y * 128, n0 = blockIdx.x * 128;
    const int tid = threadIdx.x;
    const int lane = tid & 31, wid = tid >> 5;
    const int wm = wid >> 2, wn = wid & 3, g = lane >> 2, tg = lane & 3;
    uint32_t sb = smem_u32(smem);

    const int len = decode_len(lens32, bz);
    const int nck = (len + CH_K - 1) / CH_K;   // av==0 beyond len (zero-invariant)

    const __half* Ah = g_avh + (size_t)(bz * TT + t0) * SS;
    const __half* Bh = g_mbthi + ((size_t)bz * DD + n0) * SS;

    float acc[4][4][4];
#pragma unroll
    for (int i = 0; i < 4; ++i)
#pragma unroll
        for (int j = 0; j < 4; ++j)
#pragma unroll
            for (int q = 0; q < 4; ++q) acc[i][j][q] = 0.f;

    ld_chunk16(sb, Ah, SS, tid);
    ld_chunk16(sb + TILE_SMEM, Bh, SS, tid);
    cp_commit();

    int buf = 0;
    for (int ck = 0; ck < nck; ++ck) {
        cp_wait0();
        __syncthreads();
        if (ck + 1 < nck) {
            uint32_t nb = sb + (buf ^ 1) * BUF2;
            size_t ko = (size_t)(ck + 1) * CH_K;
            ld_chunk16(nb, Ah + ko, SS, tid);
            ld_chunk16(nb + TILE_SMEM, Bh + ko, SS, tid);
            cp_commit();
        }
        mma_chunk16_1(smem + buf * BUF2, wm, wn, g, tg, acc);
        buf ^= 1;
    }

#pragma unroll
    for (int mt = 0; mt < 4; ++mt) {
#pragma unroll
        for (int h = 0; h < 2; ++h) {
            int row = wm * 64 + mt * 16 + h * 8 + g;
            __half* chrow = g_chi + (size_t)(bz * TT + t0 + row) * DD + n0;
#pragma unroll
            for (int nt = 0; nt < 4; ++nt) {
                int col = wn * 32 + nt * 8 + tg * 2;
                *(__half2*)(chrow + col) =
                    __halves2half2(__float2half_rn(acc[mt][nt][h * 2 + 0]),
                                   __float2half_rn(acc[mt][nt][h * 2 + 1]));
            }
        }
    }
}

// ---------------- GEMM3: attn_h = tanh([c, source] @ W_out); c 2-term, src 3-term ----------------
__global__ void __launch_bounds__(256) k_gemm3_mma(float* __restrict__ outh) {
    extern __shared__ char smem[];
    const int m0 = blockIdx.y * 128, n0 = blockIdx.x * 128;
    const int tid = threadIdx.x;
    const int lane = tid & 31, wid = tid >> 5;
    const int wm = wid >> 2, wn = wid & 3, g = lane >> 2, tg = lane & 3;
    uint32_t sb = smem_u32(smem);
    const int nck = (2 * DD) / CH_K;   // 8 chunks: 0-3 from c (2-term), 4-7 from src (3-term)

    float acc[4][4][4];
#pragma unroll
    for (int i = 0; i < 4; ++i)
#pragma unroll
        for (int j = 0; j < 4; ++j)
#pragma unroll
            for (int q = 0; q < 4; ++q) acc[i][j][q] = 0.f;

    auto ld_g3 = [&](uint32_t stbase, int ck) {
        const __half* Bh = g_wthi + (size_t)n0 * (2 * DD) + ck * CH_K;
        const __half* Bl = g_wtlo + (size_t)n0 * (2 * DD) + ck * CH_K;
        if (ck < 4) {
            // c chunk: single A tile (chi), skip Al slot
            ld_chunk16(stbase + 0 * TILE_SMEM, g_chi + (size_t)m0 * DD + ck * CH_K, DD, tid);
        } else {
            ld_chunk16(stbase + 0 * TILE_SMEM, g_srchi + (size_t)m0 * DD + (ck - 4) * CH_K, DD, tid);
            ld_chunk16(stbase + 1 * TILE_SMEM, g_srclo + (size_t)m0 * DD + (ck - 4) * CH_K, DD, tid);
        }
        ld_chunk16(stbase + 2 * TILE_SMEM, Bh, 2 * DD, tid);
        ld_chunk16(stbase + 3 * TILE_SMEM, Bl, 2 * DD, tid);
        cp_commit();
    };

    ld_g3(sb, 0);
    int buf = 0;
    for (int ck = 0; ck < nck; ++ck) {
        cp_wait0();
        __syncthreads();
        if (ck + 1 < nck) ld_g3(sb + (buf ^ 1) * BUF_SZ, ck + 1);
        if (ck < 4)
            mma_chunk16_2(smem + buf * BUF_SZ, wm, wn, g, tg, acc);
        else
            mma_chunk16(smem + buf * BUF_SZ, wm, wn, g, tg, acc);
        buf ^= 1;
    }

#pragma unroll
    for (int mt = 0; mt < 4; ++mt) {
#pragma unroll
        for (int h = 0; h < 2; ++h) {
            int row = wm * 64 + mt * 16 + h * 8 + g;
            float* orow = outh + (size_t)(m0 + row) * DD + n0;
#pragma unroll
            for (int nt = 0; nt < 4; ++nt) {
                int col = wn * 32 + nt * 8 + tg * 2;
                *(float2*)(orow + col) = make_float2(tanhf(acc[mt][nt][h * 2 + 0]),
                                                     tanhf(acc[mt][nt][h * 2 + 1]));
            }
        }
    }
}

// ---------------- launch ----------------
extern "C" void kernel_launch(void* const* d_in, const int* in_sizes, int n_in,
                              void* d_out, int out_size) {
    const float* src  = (const float*)d_in[0];      // [B,T,D]
    const float* mb   = (const float*)d_in[1];      // [B,S,D]
    const float* W    = (const float*)d_in[2];      // [2D,D]
    const int*   lens = (const int*)d_in[3];        // [B] (int32 or int64; decoded in-kernel)

    float* outh = (float*)d_out;                    // attn_h   [B,T,D]
    float* av   = outh + (size_t)BB * TT * DD;      // align_vectors [B,T,S]

    cudaFuncSetAttribute(k_gemm1_mma, cudaFuncAttributeMaxDynamicSharedMemorySize, GSM_TOTAL);
    cudaFuncSetAttribute(k_gemm2_mma, cudaFuncAttributeMaxDynamicSharedMemorySize, GSM2);
    cudaFuncSetAttribute(k_gemm3_mma, cudaFuncAttributeMaxDynamicSharedMemorySize, GSM_TOTAL);

    __half* srchi; cudaGetSymbolAddress((void**)&srchi, g_srchi);
    __half* srclo; cudaGetSymbolAddress((void**)&srclo, g_srclo);

    k_wsplit<<<dim3((2 * DD) / 32, DD / 32, 1), 256>>>(W);   // + rowmax init
    {
        int n4 = (BB * TT * DD) / 4;
        k_split_h<<<(n4 + 255) / 256, 256>>>((const float4*)src, srchi, srclo, n4);
    }
    k_mbsplit<<<dim3(SS / 32, DD / 32, BB), 256>>>(mb);      // mbhi + mblo + mbthi, one read

    k_gemm1_mma<<<dim3(SS / 128, TT / 128, BB), 256, GSM_TOTAL>>>(lens);

    k_colsum<<<dim3(SS / 256, NCHUNK, BB), 256>>>(lens);
    k_scan<<<(BB * SS + 255) / 256, 256>>>();
    k_phasec<<<dim3(SS / 256, NCHUNK, BB), 256>>>(lens);
    k_normsplit<<<BB * TT, 256>>>(av, lens);                  // in-CTA rowsum fused

    k_gemm2_mma<<<dim3(DD / 128, TT / 128, BB), 256, GSM2>>>(lens);
    k_gemm3_mma<<<dim3(DD / 128, (BB * TT) / 128, 1), 256, GSM_TOTAL>>>(outh);
}